// round 11
// baseline (speedup 1.0000x reference)
#include <cuda_runtime.h>
#include <cuda_bf16.h>
#include <cstdint>

#define N_IMG 64
#define IMG_ELEMS (3 * 512 * 512)          // 786432
#define BINS 256

#define THREADS 192                         // 6 warps
#define CHUNK   12288                       // 64 elems/thread -> u8 counts safe
#define CPI     (IMG_ELEMS / CHUNK)         // 64 sibling blocks per image
#define NBLOCKS (N_IMG * CPI)               // 4096 -> ~7 waves -> fine stagger
#define ITERS   (CHUNK / 4 / THREADS)       // 16 float4 iters (= idx regs/thread)
#define H_WORDS (THREADS * BINS / 4)        // 12288 u32 = 48 KB private hists
#define DYN_SMEM (H_WORDS * 4)              // 49152 B -> 4 blocks/SM

// ---------------- global coordination state -----------------------------------
__device__ unsigned int g_minmax[2 * N_IMG];   // enc(min), enc(max)
__device__ int g_hist[N_IMG * BINS];
__device__ int g_cnt1[N_IMG];                  // minmax arrivals
__device__ int g_cnt2[N_IMG];                  // hist arrivals

__device__ __forceinline__ unsigned fenc(float f) {
    unsigned u = __float_as_uint(f);
    return (u & 0x80000000u) ? ~u : (u | 0x80000000u);
}
__device__ __forceinline__ float fdec(unsigned u) {
    u = (u & 0x80000000u) ? (u ^ 0x80000000u) : ~u;
    return __uint_as_float(u);
}

// ---------------- k0: reset all coordination state (every replay!) ------------
__global__ void k_init() {
    int gt = blockIdx.x * 256 + threadIdx.x;       // 16384 = N_IMG*BINS
    g_hist[gt] = 0;
    if (gt < N_IMG) {
        g_minmax[gt] = 0xFFFFFFFFu;
        g_minmax[N_IMG + gt] = 0u;
        g_cnt1[gt] = 0;
        g_cnt2[gt] = 0;
    }
}

// ---------------- fused equalize: minmax -> hist -> cdf -> gather -------------
__global__ void __launch_bounds__(THREADS, 4)
k_equalize(const float4* __restrict__ x, float4* __restrict__ out) {
    extern __shared__ uint32_t shw[];               // 48 KB private hists, then lut
    unsigned char* sh = reinterpret_cast<unsigned char*>(shw);
    float* lutf = reinterpret_cast<float*>(shw);

    int b = blockIdx.x, t = threadIdx.x;
    int img = b / CPI;
    int base4 = b * (CHUNK / 4);
    unsigned lane = t & 31u;
    unsigned wreg = (unsigned)(t >> 5);
    unsigned cbase = wreg * 8192u + lane * 4u;       // bank == lane hist column

    __shared__ float smn[6], smx[6];

    // ---- P1: block minmax over my chunk ----
    float mn = 3.4e38f, mx = -3.4e38f;
#pragma unroll 8
    for (int i = 0; i < ITERS; i++) {
        float4 v = x[base4 + i * THREADS + t];
        mn = fminf(mn, fminf(fminf(v.x, v.y), fminf(v.z, v.w)));
        mx = fmaxf(mx, fmaxf(fmaxf(v.x, v.y), fmaxf(v.z, v.w)));
    }
#pragma unroll
    for (int o = 16; o > 0; o >>= 1) {
        mn = fminf(mn, __shfl_xor_sync(0xffffffffu, mn, o));
        mx = fmaxf(mx, __shfl_xor_sync(0xffffffffu, mx, o));
    }
    if (lane == 0) { smn[wreg] = mn; smx[wreg] = mx; }
    __syncthreads();
    if (t == 0) {
#pragma unroll
        for (int i = 1; i < 6; i++) {
            mn = fminf(mn, smn[i]);
            mx = fmaxf(mx, smx[i]);
        }
        atomicMin(&g_minmax[img], fenc(mn));
        atomicMax(&g_minmax[N_IMG + img], fenc(mx));
        __threadfence();
        atomicAdd(&g_cnt1[img], 1);
    }
    // zero private hists while waiting (overlaps the barrier)
    uint4* shv = reinterpret_cast<uint4*>(shw);
#pragma unroll
    for (int i = 0; i < H_WORDS / 4 / THREADS; i++)
        shv[t + i * THREADS] = make_uint4(0, 0, 0, 0);
    if (t == 0) {
        while (*((volatile int*)&g_cnt1[img]) < CPI) __nanosleep(64);
        __threadfence();
    }
    __syncthreads();

    float gmn = fdec(__ldcg(&g_minmax[img]));
    float gmx = fdec(__ldcg(&g_minmax[N_IMG + img]));
    float inv = 1.0f / (gmx - gmn + 1e-8f);

    // ---- P2: bucket (L2-hot re-read), idx -> registers, bank==lane hists ----
    uint32_t idxr[ITERS];
#pragma unroll
    for (int i = 0; i < ITERS; i++) {
        float4 v = __ldcs(&x[base4 + i * THREADS + t]);   // last read: evict
        unsigned b0 = (unsigned)(int)fminf(fmaxf((v.x - gmn) * 255.0f * inv, 0.0f), 255.0f);
        unsigned b1 = (unsigned)(int)fminf(fmaxf((v.y - gmn) * 255.0f * inv, 0.0f), 255.0f);
        unsigned b2 = (unsigned)(int)fminf(fmaxf((v.z - gmn) * 255.0f * inv, 0.0f), 255.0f);
        unsigned b3 = (unsigned)(int)fminf(fmaxf((v.w - gmn) * 255.0f * inv, 0.0f), 255.0f);
        idxr[i] = b0 | (b1 << 8) | (b2 << 16) | (b3 << 24);
        sh[cbase + (b0 >> 2) * 128u + (b0 & 3u)]++;
        sh[cbase + (b1 >> 2) * 128u + (b1 & 3u)]++;
        sh[cbase + (b2 >> 2) * 128u + (b2 & 3u)]++;
        sh[cbase + (b3 >> 2) * 128u + (b3 & 3u)]++;
    }
    __syncthreads();

    // ---- P3: reduce private hists -> g_hist (lane-staggered, conflict-free) --
    {
        int q = t & 63, g = t >> 6;                       // g in 0..2
        uint32_t s02 = 0, s13 = 0;
#pragma unroll
        for (int r = 0; r < 2; r++) {
            int w2 = g * 2 + r;
#pragma unroll 8
            for (int i = 0; i < 32; i++) {
                int l = (i + t) & 31;
                uint32_t v = shw[w2 * 2048 + q * 32 + l];
                s02 += v & 0x00FF00FFu;
                s13 += (v >> 8) & 0x00FF00FFu;
            }
        }
        __syncthreads();
        shw[t * 2] = s02;
        shw[t * 2 + 1] = s13;
        __syncthreads();
        if (t < 64) {
            uint32_t a02 = shw[t * 2]     + shw[(64 + t) * 2]     + shw[(128 + t) * 2];
            uint32_t a13 = shw[t * 2 + 1] + shw[(64 + t) * 2 + 1] + shw[(128 + t) * 2 + 1];
            int base = img * BINS + t * 4;
            atomicAdd(&g_hist[base + 0], (int)(a02 & 0xFFFFu));
            atomicAdd(&g_hist[base + 1], (int)(a13 & 0xFFFFu));
            atomicAdd(&g_hist[base + 2], (int)(a02 >> 16));
            atomicAdd(&g_hist[base + 3], (int)(a13 >> 16));
        }
        __syncthreads();
        if (t == 0) {
            __threadfence();
            atomicAdd(&g_cnt2[img], 1);
            while (*((volatile int*)&g_cnt2[img]) < CPI) __nanosleep(64);
            __threadfence();
        }
        __syncthreads();
    }

    // ---- P4a: warp 0 scans the 256-bin cdf, LUT into smem ----
    if (t < 32) {
        int loc[8];
        int s = 0;
#pragma unroll
        for (int j = 0; j < 8; j++) {
            s += __ldcg(&g_hist[img * BINS + t * 8 + j]);
            loc[j] = s;                                    // inclusive within lane
        }
        int sc = s;
#pragma unroll
        for (int o = 1; o < 32; o <<= 1) {
            int n = __shfl_up_sync(0xffffffffu, sc, (unsigned)o);
            if (t >= o) sc += n;
        }
        int excl = sc - s;
        float c0   = (float)__shfl_sync(0xffffffffu, loc[0], 0);  // cdf[0]
        float ctot = (float)__shfl_sync(0xffffffffu, sc, 31);     // cdf[255]
        float dinv = 1.0f / (ctot - c0 + 1e-8f);
#pragma unroll
        for (int j = 0; j < 8; j++)
            lutf[t * 8 + j] = ((float)(excl + loc[j]) - c0) * dinv;
    }
    __syncthreads();

    // ---- P4b: gather from register idx, stream out ----
#pragma unroll
    for (int i = 0; i < ITERS; i++) {
        uint32_t u = idxr[i];
        float4 r;
        r.x = lutf[u & 0xFFu];
        r.y = lutf[(u >> 8) & 0xFFu];
        r.z = lutf[(u >> 16) & 0xFFu];
        r.w = lutf[u >> 24];
        __stcs(&out[base4 + i * THREADS + t], r);
    }
}

// ---------------- launch -------------------------------------------------------
extern "C" void kernel_launch(void* const* d_in, const int* in_sizes, int n_in,
                              void* d_out, int out_size) {
    const float4* x = reinterpret_cast<const float4*>(d_in[0]);
    float4* out = reinterpret_cast<float4*>(d_out);

    static bool configured = false;
    if (!configured) {
        cudaFuncSetAttribute(k_equalize,
                             cudaFuncAttributeMaxDynamicSharedMemorySize, DYN_SMEM);
        configured = true;
    }
    k_init    <<<N_IMG, 256>>>();
    k_equalize<<<NBLOCKS, THREADS, DYN_SMEM>>>(x, out);
}

// round 12
// speedup vs baseline: 1.0617x; 1.0617x over previous
#include <cuda_runtime.h>
#include <cuda_bf16.h>
#include <cstdint>

#define N_IMG 64
#define IMG_ELEMS (3 * 512 * 512)          // 786432
#define BINS 256

#define THREADS 192                         // 6 warps
#define CHUNK   24576                       // 128 elems/thread -> u8 counts safe
#define CPI     (IMG_ELEMS / CHUNK)         // 32 sibling blocks per image
#define NBLOCKS (N_IMG * CPI)               // 2048
#define ITERS   (CHUNK / 4 / THREADS)       // 32 float4 iters (= idx regs/thread)
#define H_WORDS (THREADS * BINS / 4)        // 12288 u32 = 48 KB private hists
#define DYN_SMEM (H_WORDS * 4)              // 49152 B -> 4 blocks/SM

// ---------------- global coordination state (all zero-init = identity) --------
// min slot stores ~fenc(min) under atomicMax; max slot stores fenc(max) under
// atomicMax. Zero is the identity for both -> no init kernel needed; the
// last-arriving block per image resets everything to zero for the next replay.
__device__ unsigned int g_minmax[2 * N_IMG];
__device__ int g_hist[N_IMG * BINS];
__device__ int g_cnt1[N_IMG];                  // minmax arrivals
__device__ int g_cnt2[N_IMG];                  // hist arrivals
__device__ int g_cnt3[N_IMG];                  // completion arrivals (reset owner)

__device__ __forceinline__ unsigned fenc(float f) {
    unsigned u = __float_as_uint(f);
    return (u & 0x80000000u) ? ~u : (u | 0x80000000u);
}
__device__ __forceinline__ float fdec(unsigned u) {
    u = (u & 0x80000000u) ? (u ^ 0x80000000u) : ~u;
    return __uint_as_float(u);
}

// ---------------- fused equalize: minmax -> hist -> cdf -> gather -> reset ----
__global__ void __launch_bounds__(THREADS, 4)
k_equalize(const float4* __restrict__ x, float4* __restrict__ out) {
    extern __shared__ uint32_t shw[];               // 48 KB private hists, then lut
    unsigned char* sh = reinterpret_cast<unsigned char*>(shw);
    float* lutf = reinterpret_cast<float*>(shw);

    int b = blockIdx.x, t = threadIdx.x;
    int img = b / CPI;
    int base4 = b * (CHUNK / 4);
    unsigned lane = t & 31u;
    unsigned wreg = (unsigned)(t >> 5);
    unsigned cbase = wreg * 8192u + lane * 4u;       // bank == lane hist column

    __shared__ float smn[6], smx[6];

    // ---- P1: block minmax, 4 independent accumulator pairs for ILP ----
    float mn0 = 3.4e38f, mn1 = 3.4e38f, mn2 = 3.4e38f, mn3 = 3.4e38f;
    float mx0 = -3.4e38f, mx1 = -3.4e38f, mx2 = -3.4e38f, mx3 = -3.4e38f;
#pragma unroll 8
    for (int i = 0; i < ITERS; i += 4) {
        float4 v0 = x[base4 + (i + 0) * THREADS + t];
        float4 v1 = x[base4 + (i + 1) * THREADS + t];
        float4 v2 = x[base4 + (i + 2) * THREADS + t];
        float4 v3 = x[base4 + (i + 3) * THREADS + t];
        mn0 = fminf(mn0, fminf(fminf(v0.x, v0.y), fminf(v0.z, v0.w)));
        mx0 = fmaxf(mx0, fmaxf(fmaxf(v0.x, v0.y), fmaxf(v0.z, v0.w)));
        mn1 = fminf(mn1, fminf(fminf(v1.x, v1.y), fminf(v1.z, v1.w)));
        mx1 = fmaxf(mx1, fmaxf(fmaxf(v1.x, v1.y), fmaxf(v1.z, v1.w)));
        mn2 = fminf(mn2, fminf(fminf(v2.x, v2.y), fminf(v2.z, v2.w)));
        mx2 = fmaxf(mx2, fmaxf(fmaxf(v2.x, v2.y), fmaxf(v2.z, v2.w)));
        mn3 = fminf(mn3, fminf(fminf(v3.x, v3.y), fminf(v3.z, v3.w)));
        mx3 = fmaxf(mx3, fmaxf(fmaxf(v3.x, v3.y), fmaxf(v3.z, v3.w)));
    }
    float mn = fminf(fminf(mn0, mn1), fminf(mn2, mn3));
    float mx = fmaxf(fmaxf(mx0, mx1), fmaxf(mx2, mx3));
#pragma unroll
    for (int o = 16; o > 0; o >>= 1) {
        mn = fminf(mn, __shfl_xor_sync(0xffffffffu, mn, o));
        mx = fmaxf(mx, __shfl_xor_sync(0xffffffffu, mx, o));
    }
    if (lane == 0) { smn[wreg] = mn; smx[wreg] = mx; }
    __syncthreads();
    if (t == 0) {
#pragma unroll
        for (int i = 1; i < 6; i++) {
            mn = fminf(mn, smn[i]);
            mx = fmaxf(mx, smx[i]);
        }
        atomicMax(&g_minmax[img], ~fenc(mn));          // zero-identity min
        atomicMax(&g_minmax[N_IMG + img], fenc(mx));   // zero-identity max
        __threadfence();
        atomicAdd(&g_cnt1[img], 1);
    }
    // zero private hists while waiting (overlaps the barrier)
    uint4* shv = reinterpret_cast<uint4*>(shw);
#pragma unroll
    for (int i = 0; i < H_WORDS / 4 / THREADS; i++)
        shv[t + i * THREADS] = make_uint4(0, 0, 0, 0);
    if (t == 0) {
        while (*((volatile int*)&g_cnt1[img]) < CPI) __nanosleep(64);
        __threadfence();
    }
    __syncthreads();

    float gmn = fdec(~__ldcg(&g_minmax[img]));
    float gmx = fdec(__ldcg(&g_minmax[N_IMG + img]));
    float inv = 1.0f / (gmx - gmn + 1e-8f);

    // ---- P2: bucket (L2-hot re-read), idx -> registers, bank==lane hists ----
    uint32_t idxr[ITERS];
#pragma unroll
    for (int i = 0; i < ITERS; i++) {
        float4 v = __ldcs(&x[base4 + i * THREADS + t]);   // last read: evict
        unsigned b0 = (unsigned)(int)fminf(fmaxf((v.x - gmn) * 255.0f * inv, 0.0f), 255.0f);
        unsigned b1 = (unsigned)(int)fminf(fmaxf((v.y - gmn) * 255.0f * inv, 0.0f), 255.0f);
        unsigned b2 = (unsigned)(int)fminf(fmaxf((v.z - gmn) * 255.0f * inv, 0.0f), 255.0f);
        unsigned b3 = (unsigned)(int)fminf(fmaxf((v.w - gmn) * 255.0f * inv, 0.0f), 255.0f);
        idxr[i] = b0 | (b1 << 8) | (b2 << 16) | (b3 << 24);
        sh[cbase + (b0 >> 2) * 128u + (b0 & 3u)]++;
        sh[cbase + (b1 >> 2) * 128u + (b1 & 3u)]++;
        sh[cbase + (b2 >> 2) * 128u + (b2 & 3u)]++;
        sh[cbase + (b3 >> 2) * 128u + (b3 & 3u)]++;
    }
    __syncthreads();

    // ---- P3: reduce private hists -> g_hist (lane-staggered, conflict-free) --
    {
        int q = t & 63, g = t >> 6;                       // g in 0..2
        uint32_t s02 = 0, s13 = 0;
#pragma unroll
        for (int r = 0; r < 2; r++) {
            int w2 = g * 2 + r;
#pragma unroll 8
            for (int i = 0; i < 32; i++) {
                int l = (i + t) & 31;
                uint32_t v = shw[w2 * 2048 + q * 32 + l];
                s02 += v & 0x00FF00FFu;
                s13 += (v >> 8) & 0x00FF00FFu;
            }
        }
        __syncthreads();
        shw[t * 2] = s02;
        shw[t * 2 + 1] = s13;
        __syncthreads();
        if (t < 64) {
            uint32_t a02 = shw[t * 2]     + shw[(64 + t) * 2]     + shw[(128 + t) * 2];
            uint32_t a13 = shw[t * 2 + 1] + shw[(64 + t) * 2 + 1] + shw[(128 + t) * 2 + 1];
            int base = img * BINS + t * 4;
            atomicAdd(&g_hist[base + 0], (int)(a02 & 0xFFFFu));
            atomicAdd(&g_hist[base + 1], (int)(a13 & 0xFFFFu));
            atomicAdd(&g_hist[base + 2], (int)(a02 >> 16));
            atomicAdd(&g_hist[base + 3], (int)(a13 >> 16));
        }
        __syncthreads();
        if (t == 0) {
            __threadfence();
            atomicAdd(&g_cnt2[img], 1);
            while (*((volatile int*)&g_cnt2[img]) < CPI) __nanosleep(64);
            __threadfence();
        }
        __syncthreads();
    }

    // ---- P4a: warp 0 scans the 256-bin cdf, LUT into smem ----
    if (t < 32) {
        int loc[8];
        int s = 0;
#pragma unroll
        for (int j = 0; j < 8; j++) {
            s += __ldcg(&g_hist[img * BINS + t * 8 + j]);
            loc[j] = s;                                    // inclusive within lane
        }
        int sc = s;
#pragma unroll
        for (int o = 1; o < 32; o <<= 1) {
            int n = __shfl_up_sync(0xffffffffu, sc, (unsigned)o);
            if (t >= o) sc += n;
        }
        int excl = sc - s;
        float c0   = (float)__shfl_sync(0xffffffffu, loc[0], 0);  // cdf[0]
        float ctot = (float)__shfl_sync(0xffffffffu, sc, 31);     // cdf[255]
        float dinv = 1.0f / (ctot - c0 + 1e-8f);
#pragma unroll
        for (int j = 0; j < 8; j++)
            lutf[t * 8 + j] = ((float)(excl + loc[j]) - c0) * dinv;
    }
    __syncthreads();     // g_hist fully consumed into lutf after this point

    // ---- P4b: gather from register idx, stream out ----
#pragma unroll
    for (int i = 0; i < ITERS; i++) {
        uint32_t u = idxr[i];
        float4 r;
        r.x = lutf[u & 0xFFu];
        r.y = lutf[(u >> 8) & 0xFFu];
        r.z = lutf[(u >> 16) & 0xFFu];
        r.w = lutf[u >> 24];
        __stcs(&out[base4 + i * THREADS + t], r);
    }

    // ---- epilogue: last-arriving sibling resets this image's state ----------
    if (t == 0) {
        int old = atomicAdd(&g_cnt3[img], 1);
        if (old == CPI - 1) {
            // everyone has consumed g_hist/g_minmax; zero for next replay
            int4* h4 = reinterpret_cast<int4*>(&g_hist[img * BINS]);
#pragma unroll 8
            for (int i = 0; i < BINS / 4; i++)
                h4[i] = make_int4(0, 0, 0, 0);
            g_minmax[img] = 0u;
            g_minmax[N_IMG + img] = 0u;
            g_cnt1[img] = 0;
            g_cnt2[img] = 0;
            g_cnt3[img] = 0;
        }
    }
}

// ---------------- launch -------------------------------------------------------
extern "C" void kernel_launch(void* const* d_in, const int* in_sizes, int n_in,
                              void* d_out, int out_size) {
    const float4* x = reinterpret_cast<const float4*>(d_in[0]);
    float4* out = reinterpret_cast<float4*>(d_out);

    static bool configured = false;
    if (!configured) {
        cudaFuncSetAttribute(k_equalize,
                             cudaFuncAttributeMaxDynamicSharedMemorySize, DYN_SMEM);
        configured = true;
    }
    k_equalize<<<NBLOCKS, THREADS, DYN_SMEM>>>(x, out);
}

// round 13
// speedup vs baseline: 1.1157x; 1.0509x over previous
#include <cuda_runtime.h>
#include <cuda_bf16.h>
#include <cstdint>

#define N_IMG 64
#define IMG_ELEMS (3 * 512 * 512)          // 786432
#define BINS 256

#define THREADS 192                         // 6 warps
#define CHUNK   24576                       // 128 elems/thread -> u8 counts safe
#define CPI     (IMG_ELEMS / CHUNK)         // 32 sibling blocks per image
#define NBLOCKS (N_IMG * CPI)               // 2048
#define ITERS   (CHUNK / 4 / THREADS)       // 32 float4 iters (= idx regs/thread)
#define H_WORDS (THREADS * BINS / 4)        // 12288 u32 = 48 KB private hists
#define DYN_SMEM (H_WORDS * 4)              // 49152 B -> 4 blocks/SM

// ---------------- global coordination state (all zero-init = identity) --------
// min slot stores ~fenc(min) under atomicMax; max slot stores fenc(max) under
// atomicMax. Zero is the identity for both -> no init kernel; the last-arriving
// block per image resets everything to zero for the next graph replay.
__device__ unsigned int g_minmax[2 * N_IMG];
__device__ int g_hist[N_IMG * BINS];
__device__ int g_cnt1[N_IMG];                  // minmax arrivals
__device__ int g_cnt2[N_IMG];                  // hist arrivals
__device__ int g_cnt3[N_IMG];                  // completion arrivals (reset owner)

__device__ __forceinline__ unsigned fenc(float f) {
    unsigned u = __float_as_uint(f);
    return (u & 0x80000000u) ? ~u : (u | 0x80000000u);
}
__device__ __forceinline__ float fdec(unsigned u) {
    u = (u & 0x80000000u) ? (u ^ 0x80000000u) : ~u;
    return __uint_as_float(u);
}

// ---------------- fused equalize: minmax -> hist -> cdf -> gather -> reset ----
__global__ void __launch_bounds__(THREADS, 4)
k_equalize(const float4* __restrict__ x, float4* __restrict__ out) {
    extern __shared__ uint32_t shw[];               // 48 KB private hists, then lut
    unsigned char* sh = reinterpret_cast<unsigned char*>(shw);
    float* lutf = reinterpret_cast<float*>(shw);

    int b = blockIdx.x, t = threadIdx.x;
    int img = b / CPI;
    int base4 = b * (CHUNK / 4);
    unsigned lane = t & 31u;
    unsigned wreg = (unsigned)(t >> 5);
    unsigned cbase = wreg * 8192u + lane * 4u;       // bank == lane hist column

    __shared__ float smn[6], smx[6];
    __shared__ int slast;

    // ---- P1: block minmax over my chunk (R6 body: serial accumulator) ----
    float mn = 3.4e38f, mx = -3.4e38f;
#pragma unroll 8
    for (int i = 0; i < ITERS; i++) {
        float4 v = x[base4 + i * THREADS + t];
        mn = fminf(mn, fminf(fminf(v.x, v.y), fminf(v.z, v.w)));
        mx = fmaxf(mx, fmaxf(fmaxf(v.x, v.y), fmaxf(v.z, v.w)));
    }
#pragma unroll
    for (int o = 16; o > 0; o >>= 1) {
        mn = fminf(mn, __shfl_xor_sync(0xffffffffu, mn, o));
        mx = fmaxf(mx, __shfl_xor_sync(0xffffffffu, mx, o));
    }
    if (lane == 0) { smn[wreg] = mn; smx[wreg] = mx; }
    __syncthreads();
    if (t == 0) {
#pragma unroll
        for (int i = 1; i < 6; i++) {
            mn = fminf(mn, smn[i]);
            mx = fmaxf(mx, smx[i]);
        }
        atomicMax(&g_minmax[img], ~fenc(mn));          // zero-identity min
        atomicMax(&g_minmax[N_IMG + img], fenc(mx));   // zero-identity max
        __threadfence();
        atomicAdd(&g_cnt1[img], 1);
    }
    // zero private hists while waiting (overlaps the barrier)
    uint4* shv = reinterpret_cast<uint4*>(shw);
#pragma unroll
    for (int i = 0; i < H_WORDS / 4 / THREADS; i++)
        shv[t + i * THREADS] = make_uint4(0, 0, 0, 0);
    if (t == 0) {
        while (*((volatile int*)&g_cnt1[img]) < CPI) __nanosleep(64);
        __threadfence();
    }
    __syncthreads();

    float gmn = fdec(~__ldcg(&g_minmax[img]));
    float gmx = fdec(__ldcg(&g_minmax[N_IMG + img]));
    float inv = 1.0f / (gmx - gmn + 1e-8f);

    // ---- P2: bucket (L2-hot re-read), idx -> registers, bank==lane hists ----
    uint32_t idxr[ITERS];
#pragma unroll
    for (int i = 0; i < ITERS; i++) {
        float4 v = __ldcs(&x[base4 + i * THREADS + t]);   // last read: evict
        unsigned b0 = (unsigned)(int)fminf(fmaxf((v.x - gmn) * 255.0f * inv, 0.0f), 255.0f);
        unsigned b1 = (unsigned)(int)fminf(fmaxf((v.y - gmn) * 255.0f * inv, 0.0f), 255.0f);
        unsigned b2 = (unsigned)(int)fminf(fmaxf((v.z - gmn) * 255.0f * inv, 0.0f), 255.0f);
        unsigned b3 = (unsigned)(int)fminf(fmaxf((v.w - gmn) * 255.0f * inv, 0.0f), 255.0f);
        idxr[i] = b0 | (b1 << 8) | (b2 << 16) | (b3 << 24);
        sh[cbase + (b0 >> 2) * 128u + (b0 & 3u)]++;
        sh[cbase + (b1 >> 2) * 128u + (b1 & 3u)]++;
        sh[cbase + (b2 >> 2) * 128u + (b2 & 3u)]++;
        sh[cbase + (b3 >> 2) * 128u + (b3 & 3u)]++;
    }
    __syncthreads();

    // ---- P3: reduce private hists -> g_hist (lane-staggered, conflict-free) --
    {
        int q = t & 63, g = t >> 6;                       // g in 0..2
        uint32_t s02 = 0, s13 = 0;
#pragma unroll
        for (int r = 0; r < 2; r++) {
            int w2 = g * 2 + r;
#pragma unroll 8
            for (int i = 0; i < 32; i++) {
                int l = (i + t) & 31;
                uint32_t v = shw[w2 * 2048 + q * 32 + l];
                s02 += v & 0x00FF00FFu;
                s13 += (v >> 8) & 0x00FF00FFu;
            }
        }
        __syncthreads();
        shw[t * 2] = s02;
        shw[t * 2 + 1] = s13;
        __syncthreads();
        if (t < 64) {
            uint32_t a02 = shw[t * 2]     + shw[(64 + t) * 2]     + shw[(128 + t) * 2];
            uint32_t a13 = shw[t * 2 + 1] + shw[(64 + t) * 2 + 1] + shw[(128 + t) * 2 + 1];
            int base = img * BINS + t * 4;
            atomicAdd(&g_hist[base + 0], (int)(a02 & 0xFFFFu));
            atomicAdd(&g_hist[base + 1], (int)(a13 & 0xFFFFu));
            atomicAdd(&g_hist[base + 2], (int)(a02 >> 16));
            atomicAdd(&g_hist[base + 3], (int)(a13 >> 16));
        }
        __syncthreads();
        if (t == 0) {
            __threadfence();
            atomicAdd(&g_cnt2[img], 1);
            while (*((volatile int*)&g_cnt2[img]) < CPI) __nanosleep(64);
            __threadfence();
        }
        __syncthreads();
    }

    // ---- P4a: warp 0 scans the 256-bin cdf, LUT into smem ----
    if (t < 32) {
        int loc[8];
        int s = 0;
#pragma unroll
        for (int j = 0; j < 8; j++) {
            s += __ldcg(&g_hist[img * BINS + t * 8 + j]);
            loc[j] = s;                                    // inclusive within lane
        }
        int sc = s;
#pragma unroll
        for (int o = 1; o < 32; o <<= 1) {
            int n = __shfl_up_sync(0xffffffffu, sc, (unsigned)o);
            if (t >= o) sc += n;
        }
        int excl = sc - s;
        float c0   = (float)__shfl_sync(0xffffffffu, loc[0], 0);  // cdf[0]
        float ctot = (float)__shfl_sync(0xffffffffu, sc, 31);     // cdf[255]
        float dinv = 1.0f / (ctot - c0 + 1e-8f);
#pragma unroll
        for (int j = 0; j < 8; j++)
            lutf[t * 8 + j] = ((float)(excl + loc[j]) - c0) * dinv;
    }
    __syncthreads();     // g_hist fully consumed into lutf after this point

    // ---- P4b: gather from register idx, stream out ----
#pragma unroll
    for (int i = 0; i < ITERS; i++) {
        uint32_t u = idxr[i];
        float4 r;
        r.x = lutf[u & 0xFFu];
        r.y = lutf[(u >> 8) & 0xFFu];
        r.z = lutf[(u >> 16) & 0xFFu];
        r.w = lutf[u >> 24];
        __stcs(&out[base4 + i * THREADS + t], r);
    }

    // ---- epilogue: last-arriving sibling resets this image's state ----------
    if (t == 0)
        slast = (atomicAdd(&g_cnt3[img], 1) == CPI - 1) ? 1 : 0;
    __syncthreads();
    if (slast) {
        // all threads of the last block zero the image's state in parallel
        if (t < BINS / 4) {
            int4* h4 = reinterpret_cast<int4*>(&g_hist[img * BINS]);
            h4[t] = make_int4(0, 0, 0, 0);
        }
        if (t == 64) g_minmax[img] = 0u;
        if (t == 65) g_minmax[N_IMG + img] = 0u;
        if (t == 66) g_cnt1[img] = 0;
        if (t == 67) g_cnt2[img] = 0;
        if (t == 68) g_cnt3[img] = 0;
    }
}

// ---------------- launch -------------------------------------------------------
extern "C" void kernel_launch(void* const* d_in, const int* in_sizes, int n_in,
                              void* d_out, int out_size) {
    const float4* x = reinterpret_cast<const float4*>(d_in[0]);
    float4* out = reinterpret_cast<float4*>(d_out);

    static bool configured = false;
    if (!configured) {
        cudaFuncSetAttribute(k_equalize,
                             cudaFuncAttributeMaxDynamicSharedMemorySize, DYN_SMEM);
        configured = true;
    }
    k_equalize<<<NBLOCKS, THREADS, DYN_SMEM>>>(x, out);
}

// round 14
// speedup vs baseline: 1.1869x; 1.0638x over previous
#include <cuda_runtime.h>
#include <cuda_bf16.h>
#include <cstdint>

#define N_IMG 64
#define IMG_ELEMS (3 * 512 * 512)          // 786432
#define BINS 256

#define THREADS 256                         // 8 warps
#define CHUNK   32768                       // 128 elems/thread -> u8 counts safe
#define CPI     (IMG_ELEMS / CHUNK)         // 24 sibling blocks per image
#define NBLOCKS (N_IMG * CPI)               // 1536
#define ITERS   (CHUNK / 4 / THREADS)       // 32 float4 iters (= idx regs/thread)
#define H_WORDS (THREADS * BINS / 4)        // 16384 u32 = 64 KB private hists
#define DYN_SMEM (H_WORDS * 4)              // 65536 B -> 3 blocks/SM (192 KB)

// ---------------- global coordination state (all zero-init = identity) --------
// min slot stores ~fenc(min) under atomicMax; max slot stores fenc(max) under
// atomicMax. Zero is the identity for both -> no init kernel; the last-arriving
// block per image resets everything to zero for the next graph replay.
__device__ unsigned int g_minmax[2 * N_IMG];
__device__ int g_hist[N_IMG * BINS];
__device__ int g_cnt1[N_IMG];                  // minmax arrivals
__device__ int g_cnt2[N_IMG];                  // hist arrivals
__device__ int g_cnt3[N_IMG];                  // completion arrivals (reset owner)

__device__ __forceinline__ unsigned fenc(float f) {
    unsigned u = __float_as_uint(f);
    return (u & 0x80000000u) ? ~u : (u | 0x80000000u);
}
__device__ __forceinline__ float fdec(unsigned u) {
    u = (u & 0x80000000u) ? (u ^ 0x80000000u) : ~u;
    return __uint_as_float(u);
}

// ---------------- fused equalize: minmax -> hist -> cdf -> gather -> reset ----
__global__ void __launch_bounds__(THREADS, 3)
k_equalize(const float4* __restrict__ x, float4* __restrict__ out) {
    extern __shared__ uint32_t shw[];               // 64 KB private hists, then lut
    unsigned char* sh = reinterpret_cast<unsigned char*>(shw);
    float* lutf = reinterpret_cast<float*>(shw);

    int b = blockIdx.x, t = threadIdx.x;
    int img = b / CPI;
    int base4 = b * (CHUNK / 4);
    unsigned lane = t & 31u;
    unsigned wreg = (unsigned)(t >> 5);              // 0..7
    unsigned cbase = wreg * 8192u + lane * 4u;       // bank == lane hist column

    __shared__ float smn[8], smx[8];
    __shared__ int slast;

    // ---- P1: block minmax over my chunk (serial accumulator - proven best) ---
    float mn = 3.4e38f, mx = -3.4e38f;
#pragma unroll 8
    for (int i = 0; i < ITERS; i++) {
        float4 v = x[base4 + i * THREADS + t];
        mn = fminf(mn, fminf(fminf(v.x, v.y), fminf(v.z, v.w)));
        mx = fmaxf(mx, fmaxf(fmaxf(v.x, v.y), fmaxf(v.z, v.w)));
    }
#pragma unroll
    for (int o = 16; o > 0; o >>= 1) {
        mn = fminf(mn, __shfl_xor_sync(0xffffffffu, mn, o));
        mx = fmaxf(mx, __shfl_xor_sync(0xffffffffu, mx, o));
    }
    if (lane == 0) { smn[wreg] = mn; smx[wreg] = mx; }
    __syncthreads();
    if (t == 0) {
#pragma unroll
        for (int i = 1; i < 8; i++) {
            mn = fminf(mn, smn[i]);
            mx = fmaxf(mx, smx[i]);
        }
        atomicMax(&g_minmax[img], ~fenc(mn));          // zero-identity min
        atomicMax(&g_minmax[N_IMG + img], fenc(mx));   // zero-identity max
        __threadfence();
        atomicAdd(&g_cnt1[img], 1);
    }
    // zero private hists while waiting (overlaps the barrier)
    uint4* shv = reinterpret_cast<uint4*>(shw);
#pragma unroll
    for (int i = 0; i < H_WORDS / 4 / THREADS; i++)
        shv[t + i * THREADS] = make_uint4(0, 0, 0, 0);
    if (t == 0) {
        while (*((volatile int*)&g_cnt1[img]) < CPI) __nanosleep(64);
        __threadfence();
    }
    __syncthreads();

    float gmn = fdec(~__ldcg(&g_minmax[img]));
    float gmx = fdec(__ldcg(&g_minmax[N_IMG + img]));
    float inv = 1.0f / (gmx - gmn + 1e-8f);

    // ---- P2: bucket (L2-hot re-read), idx -> registers, bank==lane hists ----
    uint32_t idxr[ITERS];
#pragma unroll
    for (int i = 0; i < ITERS; i++) {
        float4 v = __ldcs(&x[base4 + i * THREADS + t]);   // last read: evict
        unsigned b0 = (unsigned)(int)fminf(fmaxf((v.x - gmn) * 255.0f * inv, 0.0f), 255.0f);
        unsigned b1 = (unsigned)(int)fminf(fmaxf((v.y - gmn) * 255.0f * inv, 0.0f), 255.0f);
        unsigned b2 = (unsigned)(int)fminf(fmaxf((v.z - gmn) * 255.0f * inv, 0.0f), 255.0f);
        unsigned b3 = (unsigned)(int)fminf(fmaxf((v.w - gmn) * 255.0f * inv, 0.0f), 255.0f);
        idxr[i] = b0 | (b1 << 8) | (b2 << 16) | (b3 << 24);
        sh[cbase + (b0 >> 2) * 128u + (b0 & 3u)]++;
        sh[cbase + (b1 >> 2) * 128u + (b1 & 3u)]++;
        sh[cbase + (b2 >> 2) * 128u + (b2 & 3u)]++;
        sh[cbase + (b3 >> 2) * 128u + (b3 & 3u)]++;
    }
    __syncthreads();

    // ---- P3: reduce private hists -> g_hist (lane-staggered, conflict-free) --
    // thread (q = t&63, g = t>>6): quad q over warp-regions {2g, 2g+1}
    {
        int q = t & 63, g = t >> 6;                       // g in 0..3
        uint32_t s02 = 0, s13 = 0;
#pragma unroll
        for (int r = 0; r < 2; r++) {
            int w2 = g * 2 + r;
#pragma unroll 8
            for (int i = 0; i < 32; i++) {
                int l = (i + t) & 31;
                uint32_t v = shw[w2 * 2048 + q * 32 + l];
                s02 += v & 0x00FF00FFu;
                s13 += (v >> 8) & 0x00FF00FFu;
            }
        }
        __syncthreads();
        shw[t * 2] = s02;
        shw[t * 2 + 1] = s13;
        __syncthreads();
        if (t < 64) {
            uint32_t a02 = shw[t * 2]           + shw[(64 + t) * 2]
                         + shw[(128 + t) * 2]   + shw[(192 + t) * 2];
            uint32_t a13 = shw[t * 2 + 1]       + shw[(64 + t) * 2 + 1]
                         + shw[(128 + t) * 2 + 1] + shw[(192 + t) * 2 + 1];
            // max 4 * 8192 = 32768 per packed half: no cross-half carry
            int base = img * BINS + t * 4;
            atomicAdd(&g_hist[base + 0], (int)(a02 & 0xFFFFu));
            atomicAdd(&g_hist[base + 1], (int)(a13 & 0xFFFFu));
            atomicAdd(&g_hist[base + 2], (int)(a02 >> 16));
            atomicAdd(&g_hist[base + 3], (int)(a13 >> 16));
        }
        __syncthreads();
        if (t == 0) {
            __threadfence();
            atomicAdd(&g_cnt2[img], 1);
            while (*((volatile int*)&g_cnt2[img]) < CPI) __nanosleep(64);
            __threadfence();
        }
        __syncthreads();
    }

    // ---- P4a: warp 0 scans the 256-bin cdf, LUT into smem ----
    if (t < 32) {
        int loc[8];
        int s = 0;
#pragma unroll
        for (int j = 0; j < 8; j++) {
            s += __ldcg(&g_hist[img * BINS + t * 8 + j]);
            loc[j] = s;                                    // inclusive within lane
        }
        int sc = s;
#pragma unroll
        for (int o = 1; o < 32; o <<= 1) {
            int n = __shfl_up_sync(0xffffffffu, sc, (unsigned)o);
            if (t >= o) sc += n;
        }
        int excl = sc - s;
        float c0   = (float)__shfl_sync(0xffffffffu, loc[0], 0);  // cdf[0]
        float ctot = (float)__shfl_sync(0xffffffffu, sc, 31);     // cdf[255]
        float dinv = 1.0f / (ctot - c0 + 1e-8f);
#pragma unroll
        for (int j = 0; j < 8; j++)
            lutf[t * 8 + j] = ((float)(excl + loc[j]) - c0) * dinv;
    }
    __syncthreads();     // g_hist fully consumed into lutf after this point

    // ---- P4b: gather from register idx, stream out ----
#pragma unroll
    for (int i = 0; i < ITERS; i++) {
        uint32_t u = idxr[i];
        float4 r;
        r.x = lutf[u & 0xFFu];
        r.y = lutf[(u >> 8) & 0xFFu];
        r.z = lutf[(u >> 16) & 0xFFu];
        r.w = lutf[u >> 24];
        __stcs(&out[base4 + i * THREADS + t], r);
    }

    // ---- epilogue: last-arriving sibling resets this image's state ----------
    if (t == 0)
        slast = (atomicAdd(&g_cnt3[img], 1) == CPI - 1) ? 1 : 0;
    __syncthreads();
    if (slast) {
        if (t < BINS / 4) {
            int4* h4 = reinterpret_cast<int4*>(&g_hist[img * BINS]);
            h4[t] = make_int4(0, 0, 0, 0);
        }
        if (t == 64) g_minmax[img] = 0u;
        if (t == 65) g_minmax[N_IMG + img] = 0u;
        if (t == 66) g_cnt1[img] = 0;
        if (t == 67) g_cnt2[img] = 0;
        if (t == 68) g_cnt3[img] = 0;
    }
}

// ---------------- launch -------------------------------------------------------
extern "C" void kernel_launch(void* const* d_in, const int* in_sizes, int n_in,
                              void* d_out, int out_size) {
    const float4* x = reinterpret_cast<const float4*>(d_in[0]);
    float4* out = reinterpret_cast<float4*>(d_out);

    static bool configured = false;
    if (!configured) {
        cudaFuncSetAttribute(k_equalize,
                             cudaFuncAttributeMaxDynamicSharedMemorySize, DYN_SMEM);
        configured = true;
    }
    k_equalize<<<NBLOCKS, THREADS, DYN_SMEM>>>(x, out);
}